// round 5
// baseline (speedup 1.0000x reference)
#include <cuda_runtime.h>

#define NB   64
#define LSEQ 512
#define NE   64
#define NH   8
#define ND   8
#define LN_EPS 1e-5f

// Scratch: projected Q/K/V in head-major layout [B, H, L, D]
static __device__ float g_qh[NB * NH * LSEQ * ND];
static __device__ float g_kh[NB * NH * LSEQ * ND];
static __device__ float g_vh[NB * NH * LSEQ * ND];

// ---------------------------------------------------------------------------
// Kernel 1: fused QKV projection.
// One block = 64 input rows. Weights transposed in smem (wT[e][c]) for
// conflict-free float4 reads; 4 rows x 4 cols register tile per thread.
// Writes head-major [B,H,L,D] so kernel 2's smem staging is coalesced.
// 1/sqrt(D) folded into Wq/bq.
// ---------------------------------------------------------------------------
struct __align__(16) Smem1 {
    float xq[64 * 68];      // input q rows, pitch 68 (bank-conflict-free)
    float xk[64 * 68];      // input k rows
    float w[3][64 * 64];    // wT[e][c] for Wq, Wk, Wv
    float bias[3][64];
};

__global__ __launch_bounds__(256, 1) void proj_kernel(
    const float* __restrict__ qin, const float* __restrict__ kin,
    const float* __restrict__ Wq, const float* __restrict__ bq,
    const float* __restrict__ Wk, const float* __restrict__ bk,
    const float* __restrict__ Wv, const float* __restrict__ bv)
{
    extern __shared__ char smem_raw[];
    Smem1& s = *reinterpret_cast<Smem1*>(smem_raw);
    const int t = threadIdx.x;
    const int row0 = blockIdx.x * 64;
    const float scale = 0.3535533905932738f; // 1/sqrt(8)

    // Load 64x64 input tiles (q and k share row indexing since Lq == Lk)
    {
        const float4* q4 = reinterpret_cast<const float4*>(qin + (size_t)row0 * NE);
        const float4* k4 = reinterpret_cast<const float4*>(kin + (size_t)row0 * NE);
        #pragma unroll
        for (int ss = 0; ss < 4; ss++) {
            int f = t + 256 * ss;           // 0..1023
            int r = f >> 4, e4 = f & 15;
            *reinterpret_cast<float4*>(&s.xq[r * 68 + e4 * 4]) = q4[f];
            *reinterpret_cast<float4*>(&s.xk[r * 68 + e4 * 4]) = k4[f];
        }
    }
    // Load + transpose weights into smem: s.w[m][e*64 + c] = W[c][e]
    {
        const float* Ws[3] = {Wq, Wk, Wv};
        #pragma unroll
        for (int m = 0; m < 3; m++) {
            float sc = (m == 0) ? scale : 1.0f;
            const float4* w4 = reinterpret_cast<const float4*>(Ws[m]);
            #pragma unroll
            for (int ss = 0; ss < 4; ss++) {
                int f = t + 256 * ss;
                int c = f >> 4, e4 = f & 15;
                float4 v = w4[f];
                s.w[m][(e4 * 4 + 0) * 64 + c] = v.x * sc;
                s.w[m][(e4 * 4 + 1) * 64 + c] = v.y * sc;
                s.w[m][(e4 * 4 + 2) * 64 + c] = v.z * sc;
                s.w[m][(e4 * 4 + 3) * 64 + c] = v.w * sc;
            }
        }
        if (t < 64) {
            s.bias[0][t] = bq[t] * scale;
            s.bias[1][t] = bk[t];
            s.bias[2][t] = bv[t];
        }
    }
    __syncthreads();

    const int rg = t >> 4;   // row group: rows rg*4 .. rg*4+3
    const int cg = t & 15;   // col group: cols cg*4 .. cg*4+3
    float* outs[3] = {g_qh, g_kh, g_vh};

    #pragma unroll
    for (int m = 0; m < 3; m++) {
        const float* xin = (m == 0) ? s.xq : s.xk;
        float acc[4][4] = {};
        #pragma unroll 16
        for (int e = 0; e < 64; e++) {
            float4 w = *reinterpret_cast<const float4*>(&s.w[m][e * 64 + cg * 4]);
            #pragma unroll
            for (int rr = 0; rr < 4; rr++) {
                float x = xin[(rg * 4 + rr) * 68 + e];
                acc[rr][0] = fmaf(x, w.x, acc[rr][0]);
                acc[rr][1] = fmaf(x, w.y, acc[rr][1]);
                acc[rr][2] = fmaf(x, w.z, acc[rr][2]);
                acc[rr][3] = fmaf(x, w.w, acc[rr][3]);
            }
        }
        const int h = cg >> 1, d0 = (cg & 1) * 4;
        #pragma unroll
        for (int rr = 0; rr < 4; rr++) {
            int row = row0 + rg * 4 + rr;
            int bb = row >> 9, pos = row & 511;
            float4 o;
            o.x = acc[rr][0] + s.bias[m][cg * 4 + 0];
            o.y = acc[rr][1] + s.bias[m][cg * 4 + 1];
            o.z = acc[rr][2] + s.bias[m][cg * 4 + 2];
            o.w = acc[rr][3] + s.bias[m][cg * 4 + 3];
            *reinterpret_cast<float4*>(
                &outs[m][(((size_t)bb * NH + h) * LSEQ + pos) * ND + d0]) = o;
        }
    }
}

// ---------------------------------------------------------------------------
// Kernel 2: attention over all heads for a 32-query tile + fused epilogue
// (Wo proj, residual, LN1, FF+ReLU, residual, LN2), plus the head-averaged
// attention-weight output accumulated in registers across heads.
// 512 threads: 16 warps; warp w owns query rows {w, w+16}; lane j owns
// m-columns {32*i + j, i<16}. Scores/probs live entirely in registers.
// ---------------------------------------------------------------------------
#define KPITCH 12  // floats per K/V smem row (48B, 4-phase-clean LDS.128)

struct __align__(16) Smem2 {
    float k[LSEQ * KPITCH];
    float v[LSEQ * KPITCH];
    float q[32 * ND];
    float ctx[32 * NE];
    float w[3][64 * 64];   // transposed: Wo, W1, W2 as wT[e][c]
    float bo[64], b1[64], b2[64];
    float g1[64], be1[64], g2[64], be2[64];
    float xrow[32 * 64];
    float hrow[32 * 64];
};

__global__ __launch_bounds__(512, 1) void attn_kernel(
    const float* __restrict__ prev,
    const float* __restrict__ Wo, const float* __restrict__ bo,
    const float* __restrict__ ln1g, const float* __restrict__ ln1b,
    const float* __restrict__ W1, const float* __restrict__ b1,
    const float* __restrict__ W2, const float* __restrict__ b2,
    const float* __restrict__ ln2g, const float* __restrict__ ln2b,
    float* __restrict__ out, float* __restrict__ attn)
{
    extern __shared__ char smem_raw[];
    Smem2& s = *reinterpret_cast<Smem2*>(smem_raw);
    const int t = threadIdx.x;
    const int bb = blockIdx.y;
    const int l0 = blockIdx.x * 32;

    // Epilogue weights (transposed) + small vectors
    {
        const float* Ws[3] = {Wo, W1, W2};
        #pragma unroll
        for (int m = 0; m < 3; m++) {
            const float4* w4 = reinterpret_cast<const float4*>(Ws[m]);
            #pragma unroll
            for (int ss = 0; ss < 2; ss++) {
                int f = t + 512 * ss;        // 0..1023
                int c = f >> 4, e4 = f & 15;
                float4 v = w4[f];
                s.w[m][(e4 * 4 + 0) * 64 + c] = v.x;
                s.w[m][(e4 * 4 + 1) * 64 + c] = v.y;
                s.w[m][(e4 * 4 + 2) * 64 + c] = v.z;
                s.w[m][(e4 * 4 + 3) * 64 + c] = v.w;
            }
        }
        if (t < 64) {
            s.bo[t] = bo[t];   s.b1[t] = b1[t];   s.b2[t] = b2[t];
            s.g1[t] = ln1g[t]; s.be1[t] = ln1b[t];
            s.g2[t] = ln2g[t]; s.be2[t] = ln2b[t];
        }
    }

    const int wid = t >> 5;  // warp id 0..15 -> rows (l0+wid), (l0+wid+16)
    const int j   = t & 31;  // lane -> m = 32*i + j

    float aaccA[16], aaccB[16];
    #pragma unroll
    for (int i = 0; i < 16; i++) { aaccA[i] = 0.f; aaccB[i] = 0.f; }

    #pragma unroll 1
    for (int h = 0; h < NH; h++) {
        __syncthreads();   // previous head's K/V reads done before overwrite
        {
            const float4* kg4 = reinterpret_cast<const float4*>(
                g_kh + ((size_t)(bb * NH + h) * LSEQ) * ND);
            const float4* vg4 = reinterpret_cast<const float4*>(
                g_vh + ((size_t)(bb * NH + h) * LSEQ) * ND);
            #pragma unroll
            for (int ss = 0; ss < 2; ss++) {
                int f = t + 512 * ss;             // 0..1023 float4s
                int m = f >> 1, half = f & 1;
                *reinterpret_cast<float4*>(&s.k[m * KPITCH + half * 4]) = kg4[f];
                *reinterpret_cast<float4*>(&s.v[m * KPITCH + half * 4]) = vg4[f];
            }
            if (t < 64) {
                const float4* qg4 = reinterpret_cast<const float4*>(
                    g_qh + ((size_t)(bb * NH + h) * LSEQ + l0) * ND);
                reinterpret_cast<float4*>(s.q)[t] = qg4[t];
            }
        }
        __syncthreads();

        float qa[8], qb[8];
        #pragma unroll
        for (int d = 0; d < 8; d++) {
            qa[d] = s.q[wid * 8 + d];
            qb[d] = s.q[(wid + 16) * 8 + d];
        }

        // ---- scores (scale already folded into Wq) ----
        float sa[16], sb[16];
        float mA = -1e30f, mB = -1e30f;
        #pragma unroll
        for (int i = 0; i < 16; i++) {
            int m = i * 32 + j;
            float4 k0 = *reinterpret_cast<const float4*>(&s.k[m * KPITCH]);
            float4 k1 = *reinterpret_cast<const float4*>(&s.k[m * KPITCH + 4]);
            float va = qa[0]*k0.x + qa[1]*k0.y + qa[2]*k0.z + qa[3]*k0.w
                     + qa[4]*k1.x + qa[5]*k1.y + qa[6]*k1.z + qa[7]*k1.w;
            float vb = qb[0]*k0.x + qb[1]*k0.y + qb[2]*k0.z + qb[3]*k0.w
                     + qb[4]*k1.x + qb[5]*k1.y + qb[6]*k1.z + qb[7]*k1.w;
            sa[i] = va; sb[i] = vb;
            mA = fmaxf(mA, va); mB = fmaxf(mB, vb);
        }
        #pragma unroll
        for (int o = 16; o >= 1; o >>= 1) {
            mA = fmaxf(mA, __shfl_xor_sync(0xffffffffu, mA, o));
            mB = fmaxf(mB, __shfl_xor_sync(0xffffffffu, mB, o));
        }
        float sumA = 0.f, sumB = 0.f;
        #pragma unroll
        for (int i = 0; i < 16; i++) {
            sa[i] = __expf(sa[i] - mA); sumA += sa[i];
            sb[i] = __expf(sb[i] - mB); sumB += sb[i];
        }
        #pragma unroll
        for (int o = 16; o >= 1; o >>= 1) {
            sumA += __shfl_xor_sync(0xffffffffu, sumA, o);
            sumB += __shfl_xor_sync(0xffffffffu, sumB, o);
        }
        const float invA = 1.0f / sumA, invB = 1.0f / sumB;
        const float nA = invA * 0.125f, nB = invB * 0.125f;  // /H for mean

        // ---- ctx accumulation + attn-weight accumulation ----
        float ca[8] = {}, cb[8] = {};
        #pragma unroll
        for (int i = 0; i < 16; i++) {
            int m = i * 32 + j;
            float4 v0 = *reinterpret_cast<const float4*>(&s.v[m * KPITCH]);
            float4 v1 = *reinterpret_cast<const float4*>(&s.v[m * KPITCH + 4]);
            float pa = sa[i], pb = sb[i];
            ca[0] = fmaf(pa, v0.x, ca[0]); ca[1] = fmaf(pa, v0.y, ca[1]);
            ca[2] = fmaf(pa, v0.z, ca[2]); ca[3] = fmaf(pa, v0.w, ca[3]);
            ca[4] = fmaf(pa, v1.x, ca[4]); ca[5] = fmaf(pa, v1.y, ca[5]);
            ca[6] = fmaf(pa, v1.z, ca[6]); ca[7] = fmaf(pa, v1.w, ca[7]);
            cb[0] = fmaf(pb, v0.x, cb[0]); cb[1] = fmaf(pb, v0.y, cb[1]);
            cb[2] = fmaf(pb, v0.z, cb[2]); cb[3] = fmaf(pb, v0.w, cb[3]);
            cb[4] = fmaf(pb, v1.x, cb[4]); cb[5] = fmaf(pb, v1.y, cb[5]);
            cb[6] = fmaf(pb, v1.z, cb[6]); cb[7] = fmaf(pb, v1.w, cb[7]);
            aaccA[i] = fmaf(pa, nA, aaccA[i]);
            aaccB[i] = fmaf(pb, nB, aaccB[i]);
        }
        #pragma unroll
        for (int d = 0; d < 8; d++) {
            float ra = ca[d], rb = cb[d];
            #pragma unroll
            for (int o = 16; o >= 1; o >>= 1) {
                ra += __shfl_xor_sync(0xffffffffu, ra, o);
                rb += __shfl_xor_sync(0xffffffffu, rb, o);
            }
            if (j == 0) {
                s.ctx[wid * 64 + h * 8 + d]        = ra * invA;
                s.ctx[(wid + 16) * 64 + h * 8 + d] = rb * invB;
            }
        }
    }

    // ---- attention-weight output (head mean), coalesced 128B per warp ----
    {
        float* pA = attn + ((size_t)bb * LSEQ + (l0 + wid)) * LSEQ;
        float* pB = attn + ((size_t)bb * LSEQ + (l0 + wid + 16)) * LSEQ;
        #pragma unroll
        for (int i = 0; i < 16; i++) {
            pA[i * 32 + j] = aaccA[i];
            pB[i * 32 + j] = aaccB[i];
        }
    }
    __syncthreads();

    // ---- fused epilogue: Wo proj + residual + LN1 + FF + residual + LN2 ----
    // Row-local: 16 threads per row (half-warp), 4 cols each.
    const int r  = t >> 4;     // 0..31
    const int cg = t & 15;     // cols cg*4 .. cg*4+3
    const size_t grow = (size_t)bb * LSEQ + l0 + r;

    float x0, x1, x2, x3;      // LN1 output (kept in regs for residual)
    {
        float a0 = s.bo[cg*4+0], a1 = s.bo[cg*4+1], a2 = s.bo[cg*4+2], a3 = s.bo[cg*4+3];
        #pragma unroll 16
        for (int e = 0; e < 64; e++) {
            float xx = s.ctx[r * 64 + e];
            float4 w = *reinterpret_cast<const float4*>(&s.w[0][e * 64 + cg * 4]);
            a0 = fmaf(xx, w.x, a0); a1 = fmaf(xx, w.y, a1);
            a2 = fmaf(xx, w.z, a2); a3 = fmaf(xx, w.w, a3);
        }
        const float4 pv = *reinterpret_cast<const float4*>(&prev[grow * NE + cg * 4]);
        a0 += pv.x; a1 += pv.y; a2 += pv.z; a3 += pv.w;

        float psum = a0 + a1 + a2 + a3;
        #pragma unroll
        for (int o = 8; o >= 1; o >>= 1) psum += __shfl_xor_sync(0xffffffffu, psum, o);
        float mu = psum * (1.0f / 64.0f);
        float d0 = a0 - mu, d1 = a1 - mu, d2 = a2 - mu, d3 = a3 - mu;
        float psq = d0*d0 + d1*d1 + d2*d2 + d3*d3;
        #pragma unroll
        for (int o = 8; o >= 1; o >>= 1) psq += __shfl_xor_sync(0xffffffffu, psq, o);
        float rs = rsqrtf(psq * (1.0f / 64.0f) + LN_EPS);
        x0 = fmaf(d0 * rs, s.g1[cg*4+0], s.be1[cg*4+0]);
        x1 = fmaf(d1 * rs, s.g1[cg*4+1], s.be1[cg*4+1]);
        x2 = fmaf(d2 * rs, s.g1[cg*4+2], s.be1[cg*4+2]);
        x3 = fmaf(d3 * rs, s.g1[cg*4+3], s.be1[cg*4+3]);
        s.xrow[r*64 + cg*4+0] = x0; s.xrow[r*64 + cg*4+1] = x1;
        s.xrow[r*64 + cg*4+2] = x2; s.xrow[r*64 + cg*4+3] = x3;
    }
    __syncwarp();

    {   // FF layer 1 + ReLU
        float a0 = s.b1[cg*4+0], a1 = s.b1[cg*4+1], a2 = s.b1[cg*4+2], a3 = s.b1[cg*4+3];
        #pragma unroll 16
        for (int e = 0; e < 64; e++) {
            float xx = s.xrow[r * 64 + e];
            float4 w = *reinterpret_cast<const float4*>(&s.w[1][e * 64 + cg * 4]);
            a0 = fmaf(xx, w.x, a0); a1 = fmaf(xx, w.y, a1);
            a2 = fmaf(xx, w.z, a2); a3 = fmaf(xx, w.w, a3);
        }
        s.hrow[r*64 + cg*4+0] = fmaxf(a0, 0.f);
        s.hrow[r*64 + cg*4+1] = fmaxf(a1, 0.f);
        s.hrow[r*64 + cg*4+2] = fmaxf(a2, 0.f);
        s.hrow[r*64 + cg*4+3] = fmaxf(a3, 0.f);
    }
    __syncwarp();

    {   // FF layer 2 + residual + LN2 + output write
        float a0 = s.b2[cg*4+0], a1 = s.b2[cg*4+1], a2 = s.b2[cg*4+2], a3 = s.b2[cg*4+3];
        #pragma unroll 16
        for (int e = 0; e < 64; e++) {
            float hh = s.hrow[r * 64 + e];
            float4 w = *reinterpret_cast<const float4*>(&s.w[2][e * 64 + cg * 4]);
            a0 = fmaf(hh, w.x, a0); a1 = fmaf(hh, w.y, a1);
            a2 = fmaf(hh, w.z, a2); a3 = fmaf(hh, w.w, a3);
        }
        a0 += x0; a1 += x1; a2 += x2; a3 += x3;  // residual

        float psum = a0 + a1 + a2 + a3;
        #pragma unroll
        for (int o = 8; o >= 1; o >>= 1) psum += __shfl_xor_sync(0xffffffffu, psum, o);
        float mu = psum * (1.0f / 64.0f);
        float d0 = a0 - mu, d1 = a1 - mu, d2 = a2 - mu, d3 = a3 - mu;
        float psq = d0*d0 + d1*d1 + d2*d2 + d3*d3;
        #pragma unroll
        for (int o = 8; o >= 1; o >>= 1) psq += __shfl_xor_sync(0xffffffffu, psq, o);
        float rs = rsqrtf(psq * (1.0f / 64.0f) + LN_EPS);

        float4 o4;
        o4.x = fmaf(d0 * rs, s.g2[cg*4+0], s.be2[cg*4+0]);
        o4.y = fmaf(d1 * rs, s.g2[cg*4+1], s.be2[cg*4+1]);
        o4.z = fmaf(d2 * rs, s.g2[cg*4+2], s.be2[cg*4+2]);
        o4.w = fmaf(d3 * rs, s.g2[cg*4+3], s.be2[cg*4+3]);
        *reinterpret_cast<float4*>(&out[grow * NE + cg * 4]) = o4;
    }
}

// ---------------------------------------------------------------------------
// Inputs (metadata order): q, k, prev_ga_output, Wq, bq, Wk, bk, Wv, bv,
//   Wo, bo, ln1_g, ln1_b, W1, b1, W2, b2, ln2_g, ln2_b
// Output: [out (B*L*E) | attn_wts (B*L*L)] concatenated, f32.
// ---------------------------------------------------------------------------
extern "C" void kernel_launch(void* const* d_in, const int* in_sizes, int n_in,
                              void* d_out, int out_size)
{
    const float* q    = (const float*)d_in[0];
    const float* k    = (const float*)d_in[1];
    const float* prev = (const float*)d_in[2];
    const float* Wq   = (const float*)d_in[3];
    const float* bq   = (const float*)d_in[4];
    const float* Wk   = (const float*)d_in[5];
    const float* bk   = (const float*)d_in[6];
    const float* Wv   = (const float*)d_in[7];
    const float* bv   = (const float*)d_in[8];
    const float* Wo   = (const float*)d_in[9];
    const float* bo   = (const float*)d_in[10];
    const float* g1   = (const float*)d_in[11];
    const float* be1  = (const float*)d_in[12];
    const float* W1   = (const float*)d_in[13];
    const float* b1   = (const float*)d_in[14];
    const float* W2   = (const float*)d_in[15];
    const float* b2   = (const float*)d_in[16];
    const float* g2   = (const float*)d_in[17];
    const float* be2  = (const float*)d_in[18];

    float* out  = (float*)d_out;
    float* attn = out + (size_t)NB * LSEQ * NE;

    cudaFuncSetAttribute(proj_kernel, cudaFuncAttributeMaxDynamicSharedMemorySize,
                         (int)sizeof(Smem1));
    cudaFuncSetAttribute(attn_kernel, cudaFuncAttributeMaxDynamicSharedMemorySize,
                         (int)sizeof(Smem2));

    proj_kernel<<<(NB * LSEQ) / 64, 256, sizeof(Smem1)>>>(
        q, k, Wq, bq, Wk, bk, Wv, bv);
    attn_kernel<<<dim3(LSEQ / 32, NB), 512, sizeof(Smem2)>>>(
        prev, Wo, bo, g1, be1, W1, b1, W2, b2, g2, be2, out, attn);
}